// round 2
// baseline (speedup 1.0000x reference)
#include <cuda_runtime.h>
#include <math.h>

// Problem constants (shapes fixed by the dataset)
constexpr int B  = 32;
constexpr int N  = 4096;
constexpr int DK = 128;
constexpr int H  = 128;
constexpr int A  = 128;
constexpr int NSPLIT = 32;          // blocks per batch row in attention pass
constexpr int CHUNK  = N / NSPLIT;  // 128 n per block

// ---------------- scratch (device globals; no allocation allowed) -------------
__device__ float g_zfea[(size_t)B * N * A];     // 64 MB precomputed encoder features
__device__ float g_e[B * N];                    // raw attention logits (per step)
__device__ float g_cov[B * N];                  // coverage state
__device__ float g_h[B * H], g_c[B * H];        // LSTM state
__device__ float g_s[B * DK];                   // context input to LSTM (s)
__device__ float g_dec[B * A];                  // dec_fea + b_attn (per step)
__device__ float g_mp[B * NSPLIT], g_lp[B * NSPLIT];
__device__ float g_ctxp[(size_t)B * NSPLIT * DK];
__device__ float g_closs[B];

// ---------------- helpers ----------------
__device__ __forceinline__ float tanh_fast(float x) {
    float y;
    asm("tanh.approx.f32 %0, %1;" : "=f"(y) : "f"(x));
    return y;
}
__device__ __forceinline__ float sigf(float x) { return 1.f / (1.f + __expf(-x)); }

// ---------------- init ----------------
__global__ void k_init(const float* __restrict__ h0, const float* __restrict__ c0) {
    int i = blockIdx.x * blockDim.x + threadIdx.x;
    if (i < B * H) { g_h[i] = h0[i]; g_c[i] = c0[i]; g_s[i] = 0.f; }
    if (i < B) g_closs[i] = 0.f;
    for (int j = i; j < B * N; j += gridDim.x * blockDim.x) g_cov[j] = 0.f;
}

// ---------------- z_fea = z @ W_z  (M=131072, N=128, K=128) ----------------
// BM=128, BN=128, BK=16, 256 threads, 8x8 thread tile.
__global__ void __launch_bounds__(256) k_zfea(const float* __restrict__ Z,
                                              const float* __restrict__ Wz) {
    __shared__ float z_s[128][17];
    __shared__ float w_s[16][128];
    const int tid  = threadIdx.x;
    const int rbase = blockIdx.x * 128;
    const int rowg = tid >> 4;   // 0..15
    const int colg = tid & 15;   // 0..15

    float acc[8][8];
#pragma unroll
    for (int i = 0; i < 8; ++i)
#pragma unroll
        for (int j = 0; j < 8; ++j) acc[i][j] = 0.f;

    for (int kk = 0; kk < 128; kk += 16) {
        // stage z tile [128 rows x 16 k]
        {
            int r = tid >> 1;
            int c = (tid & 1) * 8;
            const float* src = Z + (size_t)(rbase + r) * 128 + kk + c;
            float4 a0 = *(const float4*)(src);
            float4 a1 = *(const float4*)(src + 4);
            z_s[r][c + 0] = a0.x; z_s[r][c + 1] = a0.y; z_s[r][c + 2] = a0.z; z_s[r][c + 3] = a0.w;
            z_s[r][c + 4] = a1.x; z_s[r][c + 5] = a1.y; z_s[r][c + 6] = a1.z; z_s[r][c + 7] = a1.w;
        }
        // stage W_z tile [16 k x 128 cols]
        {
            int kr = tid >> 4;
            int c  = (tid & 15) * 8;
            const float* src = Wz + (size_t)(kk + kr) * 128 + c;
            float4 a0 = *(const float4*)(src);
            float4 a1 = *(const float4*)(src + 4);
            *(float4*)&w_s[kr][c]     = a0;
            *(float4*)&w_s[kr][c + 4] = a1;
        }
        __syncthreads();
#pragma unroll
        for (int k = 0; k < 16; ++k) {
            float za[8];
#pragma unroll
            for (int i = 0; i < 8; ++i) za[i] = z_s[rowg * 8 + i][k];
            float4 wb0 = *(const float4*)&w_s[k][colg * 8];
            float4 wb1 = *(const float4*)&w_s[k][colg * 8 + 4];
            float wb[8] = {wb0.x, wb0.y, wb0.z, wb0.w, wb1.x, wb1.y, wb1.z, wb1.w};
#pragma unroll
            for (int i = 0; i < 8; ++i)
#pragma unroll
                for (int j = 0; j < 8; ++j) acc[i][j] = fmaf(za[i], wb[j], acc[i][j]);
        }
        __syncthreads();
    }
#pragma unroll
    for (int i = 0; i < 8; ++i) {
        int r = rbase + rowg * 8 + i;
        float4 o0 = {acc[i][0], acc[i][1], acc[i][2], acc[i][3]};
        float4 o1 = {acc[i][4], acc[i][5], acc[i][6], acc[i][7]};
        *(float4*)(g_zfea + (size_t)r * 128 + colg * 8)     = o0;
        *(float4*)(g_zfea + (size_t)r * 128 + colg * 8 + 4) = o1;
    }
}

// ---------------- LSTM cell + dec_fea (per-b, 256 threads) ----------------
// sh must hold 1664 floats.
__device__ __forceinline__ void lstm_and_dec(
    int b, int tid,
    const float* __restrict__ Wih, const float* __restrict__ Whh,
    const float* __restrict__ bih, const float* __restrict__ bhh,
    const float* __restrict__ Wx,  const float* __restrict__ battn,
    float* sh)
{
    float* sh_s = sh;           // 128
    float* sh_h = sh + 128;     // 128
    float* sh_c = sh + 256;     // 128
    float* sh_part = sh + 384;  // 1024 (2 halves x 4 gates x 128)
    float* sh_hn = sh + 1408;   // 128
    float* sh_cn = sh + 1536;   // 128

    if (tid < 128) {
        sh_s[tid] = g_s[b * DK + tid];
        sh_h[tid] = g_h[b * H + tid];
        sh_c[tid] = g_c[b * H + tid];
    }
    __syncthreads();

    const int j = tid & 127;
    const int half = tid >> 7;
    const float* xv = half ? sh_h : sh_s;
    const float* Wb = half ? Whh : Wih;
#pragma unroll
    for (int g = 0; g < 4; ++g) {
        const float4* wr = (const float4*)(Wb + (size_t)(g * 128 + j) * 128);
        float acc = 0.f;
#pragma unroll 8
        for (int d = 0; d < 32; ++d) {
            float4 w = wr[d];
            acc = fmaf(w.x, xv[4 * d + 0], acc);
            acc = fmaf(w.y, xv[4 * d + 1], acc);
            acc = fmaf(w.z, xv[4 * d + 2], acc);
            acc = fmaf(w.w, xv[4 * d + 3], acc);
        }
        sh_part[half * 512 + g * 128 + j] = acc;
    }
    __syncthreads();

    if (tid < 128) {
        float gi = sh_part[0   + tid] + sh_part[512 + tid] + bih[tid]       + bhh[tid];
        float gf = sh_part[128 + tid] + sh_part[640 + tid] + bih[128 + tid] + bhh[128 + tid];
        float gg = sh_part[256 + tid] + sh_part[768 + tid] + bih[256 + tid] + bhh[256 + tid];
        float go = sh_part[384 + tid] + sh_part[896 + tid] + bih[384 + tid] + bhh[384 + tid];
        float cn = sigf(gf) * sh_c[tid] + sigf(gi) * tanhf(gg);
        float hn = sigf(go) * tanhf(cn);
        sh_hn[tid] = hn; sh_cn[tid] = cn;
        g_h[b * H + tid] = hn;
        g_c[b * H + tid] = cn;
    }
    __syncthreads();

    if (tid < 128) {
        float acc = battn[tid];
#pragma unroll 4
        for (int k = 0; k < 128; ++k) {
            acc = fmaf(sh_hn[k], Wx[(size_t)k * A + tid], acc);
            acc = fmaf(sh_cn[k], Wx[(size_t)(128 + k) * A + tid], acc);
        }
        g_dec[b * A + tid] = acc;
    }
}

__global__ void __launch_bounds__(256) k_lstm0(
    const float* __restrict__ Wih, const float* __restrict__ Whh,
    const float* __restrict__ bih, const float* __restrict__ bhh,
    const float* __restrict__ Wx,  const float* __restrict__ battn)
{
    __shared__ float sh[1664];
    lstm_and_dec(blockIdx.x, threadIdx.x, Wih, Whh, bih, bhh, Wx, battn, sh);
}

// ---------------- attention main pass (online softmax + context partials) ----
__global__ void __launch_bounds__(256) k_attn(
    const float* __restrict__ Z, const float* __restrict__ mask,
    const float* __restrict__ wc, const float* __restrict__ v)
{
    const int b = blockIdx.y;
    const int split = blockIdx.x;
    const int nbase = split * CHUNK;
    const int tid = threadIdx.x;
    const int lane = tid & 31;
    const int warp = tid >> 5;

    __shared__ float sh_cov[CHUNK];
    __shared__ float sh_msk[CHUNK];
    __shared__ float sh_wm[8], sh_wl[8];
    __shared__ float sh_wctx[8][128];

    if (tid < CHUNK) {
        sh_cov[tid] = g_cov[b * N + nbase + tid];
        sh_msk[tid] = mask[b * N + nbase + tid];
    }
    const float4 dec4 = ((const float4*)(g_dec + b * A))[lane];
    const float4 wc4  = ((const float4*)wc)[lane];
    const float4 v4   = ((const float4*)v)[lane];
    __syncthreads();

    float m = -3.0e38f, l = 0.f;
    float4 ctx = {0.f, 0.f, 0.f, 0.f};

    const float4* zfb = (const float4*)g_zfea + (size_t)b * N * 32;
    const float4* zb  = (const float4*)Z      + (size_t)b * N * 32;

    const int nloc0 = warp * 16;
    float4 zf = zfb[(size_t)(nbase + nloc0) * 32 + lane];
    float4 zv = zb [(size_t)(nbase + nloc0) * 32 + lane];

#pragma unroll
    for (int i = 0; i < 16; ++i) {
        const int nloc = nloc0 + i;
        float4 zf_c = zf, zv_c = zv;
        if (i < 15) {  // prefetch next n (2 loads in flight per warp)
            zf = zfb[(size_t)(nbase + nloc + 1) * 32 + lane];
            zv = zb [(size_t)(nbase + nloc + 1) * 32 + lane];
        }
        const float cov = sh_cov[nloc];
        float f0 = tanh_fast(fmaf(cov, wc4.x, zf_c.x + dec4.x));
        float f1 = tanh_fast(fmaf(cov, wc4.y, zf_c.y + dec4.y));
        float f2 = tanh_fast(fmaf(cov, wc4.z, zf_c.z + dec4.z));
        float f3 = tanh_fast(fmaf(cov, wc4.w, zf_c.w + dec4.w));
        float part = v4.x * f0 + v4.y * f1 + v4.z * f2 + v4.w * f3;
#pragma unroll
        for (int o = 16; o; o >>= 1) part += __shfl_xor_sync(0xffffffffu, part, o);
        float e = (sh_msk[nloc] > 0.f) ? part : -1e9f;
        if (lane == 0) g_e[b * N + nbase + nloc] = e;

        // online softmax + context accumulation
        float nm = fmaxf(m, e);
        float sc = __expf(m - nm);
        float p  = __expf(e - nm);
        l = l * sc + p;
        ctx.x = fmaf(p, zv_c.x, ctx.x * sc);
        ctx.y = fmaf(p, zv_c.y, ctx.y * sc);
        ctx.z = fmaf(p, zv_c.z, ctx.z * sc);
        ctx.w = fmaf(p, zv_c.w, ctx.w * sc);
        m = nm;
    }

    sh_wctx[warp][lane * 4 + 0] = ctx.x;
    sh_wctx[warp][lane * 4 + 1] = ctx.y;
    sh_wctx[warp][lane * 4 + 2] = ctx.z;
    sh_wctx[warp][lane * 4 + 3] = ctx.w;
    if (lane == 0) { sh_wm[warp] = m; sh_wl[warp] = l; }
    __syncthreads();

    if (tid < 128) {
        float M = sh_wm[0];
#pragma unroll
        for (int w = 1; w < 8; ++w) M = fmaxf(M, sh_wm[w]);
        float acc = 0.f;
#pragma unroll
        for (int w = 0; w < 8; ++w) acc = fmaf(sh_wctx[w][tid], __expf(sh_wm[w] - M), acc);
        g_ctxp[((size_t)b * NSPLIT + split) * 128 + tid] = acc;
        if (tid == 0) {
            float L = 0.f;
#pragma unroll
            for (int w = 0; w < 8; ++w) L = fmaf(sh_wl[w], __expf(sh_wm[w] - M), L);
            g_mp[b * NSPLIT + split] = M;
            g_lp[b * NSPLIT + split] = L;
        }
    }
}

// --------- combine partials + finalize attn/coverage/closs + next LSTM -------
__global__ void __launch_bounds__(256) k_finish(
    int t, int T, float* __restrict__ out,
    const float* __restrict__ Wih, const float* __restrict__ Whh,
    const float* __restrict__ bih, const float* __restrict__ bhh,
    const float* __restrict__ Wx,  const float* __restrict__ battn)
{
    const int b = blockIdx.x;
    const int tid = threadIdx.x;
    __shared__ float sh_m[NSPLIT], sh_l[NSPLIT], sh_scale[NSPLIT];
    __shared__ float sh_red[256];
    __shared__ float sh_lstm[1664];

    if (tid < NSPLIT) {
        sh_m[tid] = g_mp[b * NSPLIT + tid];
        sh_l[tid] = g_lp[b * NSPLIT + tid];
    }
    __syncthreads();
    float M = sh_m[0];
#pragma unroll
    for (int s = 1; s < NSPLIT; ++s) M = fmaxf(M, sh_m[s]);
    if (tid < NSPLIT) sh_scale[tid] = __expf(sh_m[tid] - M);
    __syncthreads();
    float L = 0.f;
#pragma unroll
    for (int s = 0; s < NSPLIT; ++s) L = fmaf(sh_l[s], sh_scale[s], L);
    const float invL = 1.f / L;

    if (tid < 128) {
        float acc = 0.f;
#pragma unroll 8
        for (int s = 0; s < NSPLIT; ++s)
            acc = fmaf(g_ctxp[((size_t)b * NSPLIT + s) * 128 + tid], sh_scale[s], acc);
        float ct = acc * invL;
        out[((size_t)b * T + t) * DK + tid] = ct;   // text output
        g_s[b * DK + tid] = ct;                     // s_new = c_t
    }

    // finalize softmax, coverage update, coverage loss
    float* attn_out = out + (size_t)B * T * DK;
    float closs = 0.f;
#pragma unroll
    for (int it = 0; it < N / 256; ++it) {
        int n = it * 256 + tid;
        float e = g_e[b * N + n];
        float p = __expf(e - M) * invL;
        float cov = g_cov[b * N + n];
        closs += fminf(p, cov);
        g_cov[b * N + n] = cov + p;
        attn_out[((size_t)b * T + t) * N + n] = p;
    }
    sh_red[tid] = closs;
    __syncthreads();
#pragma unroll
    for (int o = 128; o; o >>= 1) {
        if (tid < o) sh_red[tid] += sh_red[tid + o];
        __syncthreads();
    }
    if (tid == 0) g_closs[b] += sh_red[0];
    __syncthreads();

    // LSTM + dec_fea for the NEXT step (uses g_s just written; harmless on last step)
    lstm_and_dec(b, tid, Wih, Whh, bih, bhh, Wx, battn, sh_lstm);
}

// ---------------- closs reduction ----------------
__global__ void k_closs(float* __restrict__ out, int T) {
    float val = (threadIdx.x < B) ? g_closs[threadIdx.x] : 0.f;
#pragma unroll
    for (int o = 16; o; o >>= 1) val += __shfl_xor_sync(0xffffffffu, val, o);
    if (threadIdx.x == 0)
        out[(size_t)B * T * DK + (size_t)B * T * N] = val / (float)B;
}

// ---------------- launch ----------------
extern "C" void kernel_launch(void* const* d_in, const int* in_sizes, int n_in,
                              void* d_out, int out_size) {
    const float* z     = (const float*)d_in[0];
    const float* mask  = (const float*)d_in[1];
    const float* h0    = (const float*)d_in[2];
    const float* c0    = (const float*)d_in[3];
    const float* Wih   = (const float*)d_in[4];
    const float* Whh   = (const float*)d_in[5];
    const float* bih   = (const float*)d_in[6];
    const float* bhh   = (const float*)d_in[7];
    const float* Wx    = (const float*)d_in[8];
    const float* Wz    = (const float*)d_in[9];
    const float* wc    = (const float*)d_in[10];
    const float* battn = (const float*)d_in[11];
    const float* v     = (const float*)d_in[12];
    float* out = (float*)d_out;

    // n_node lives on device; recover step count from the output element count:
    // out_size = B*T*DK + B*T*N + 1
    const int T = (out_size - 1) / (B * (DK + N));

    k_init<<<512, 256>>>(h0, c0);
    k_zfea<<<1024, 256>>>(z, Wz);
    k_lstm0<<<B, 256>>>(Wih, Whh, bih, bhh, Wx, battn);
    for (int t = 0; t < T; ++t) {
        k_attn<<<dim3(NSPLIT, B), 256>>>(z, mask, wc, v);
        k_finish<<<B, 256>>>(t, T, out, Wih, Whh, bih, bhh, Wx, battn);
    }
    k_closs<<<1, 32>>>(out, T);
}